// round 7
// baseline (speedup 1.0000x reference)
#include <cuda_runtime.h>
#include <cuda_bf16.h>
#include <math.h>
#include <stdint.h>

#define HID 1024
#define VOC 32000
#define MEMN 32
#define BAT 32
#define TN 64
#define RN (TN*BAT)      // 2048
#define G3 (3*HID)       // 3072
#define SLOT (BAT*HID)   // 32768

// ---------------- device scratch (static, no allocs) ----------------
__device__ __align__(16) __nv_bfloat16 g_Wout[(size_t)VOC*HID];
__device__ __align__(16) __nv_bfloat16 g_Wih3[(size_t)G3*HID];   // bf16, rows permuted: 3*h+g
__device__ __align__(16) float g_Whh3f[(size_t)G3*HID];          // f32, rows permuted: 3*h+g
__device__ __align__(16) float g_bih3[G3];
__device__ __align__(16) float g_bhh3[G3];
__device__ __align__(16) __nv_bfloat16 g_Wp1[(size_t)HID*HID];   // bf16 x-half of W_proj
__device__ __align__(16) float g_Wp2f[(size_t)HID*HID];          // f32 mem-half of W_proj
__device__ __align__(16) __nv_bfloat16 g_xbf[(size_t)RN*HID];    // relu(emb), rows (t*B+b)
__device__ __align__(16) float         g_S  [(size_t)(MEMN+TN)*SLOT];  // state ring, f32
__device__ __align__(16) __nv_bfloat16 g_Sbf[(size_t)(MEMN+TN)*SLOT];  // state ring, bf16 (vocab GEMM)
__device__ __align__(16) float g_giAll[(size_t)RN*G3];           // x@W_ih^T+b_ih (perm cols)
__device__ __align__(16) float g_projA[(size_t)RN*HID];          // x@Wp1^T+b_proj
__device__ __align__(16) float g_proj[(size_t)BAT*HID];
__device__ __align__(16) float g_sel[(size_t)BAT*HID];
__device__ __align__(16) float g_logits[(size_t)RN*VOC];
__device__ float g_lse[RN];

// ---------------- mma helpers ----------------
__device__ __forceinline__ unsigned su32(const void* p) {
    return (unsigned)__cvta_generic_to_shared(p);
}
__device__ __forceinline__ void ldmx4(unsigned* r, unsigned a) {
    asm volatile("ldmatrix.sync.aligned.m8n8.x4.shared.b16 {%0,%1,%2,%3},[%4];"
                 : "=r"(r[0]), "=r"(r[1]), "=r"(r[2]), "=r"(r[3]) : "r"(a));
}
__device__ __forceinline__ void ldmx2(unsigned* r, unsigned a) {
    asm volatile("ldmatrix.sync.aligned.m8n8.x2.shared.b16 {%0,%1},[%2];"
                 : "=r"(r[0]), "=r"(r[1]) : "r"(a));
}
__device__ __forceinline__ void mma16816(float* c, const unsigned* a, const unsigned* b) {
    asm volatile(
        "mma.sync.aligned.m16n8k16.row.col.f32.bf16.bf16.f32 "
        "{%0,%1,%2,%3},{%4,%5,%6,%7},{%8,%9},{%0,%1,%2,%3};"
        : "+f"(c[0]), "+f"(c[1]), "+f"(c[2]), "+f"(c[3])
        : "r"(a[0]), "r"(a[1]), "r"(a[2]), "r"(a[3]), "r"(b[0]), "r"(b[1]));
}
// tf32 m16n8k8
__device__ __forceinline__ uint32_t f2tf(float f) {
    uint32_t r;
    asm("cvt.rna.tf32.f32 %0, %1;" : "=r"(r) : "f"(f));
    return r;
}
__device__ __forceinline__ void mma1688tf(float* c, const uint32_t* a, const uint32_t* b) {
    asm volatile(
        "mma.sync.aligned.m16n8k8.row.col.f32.tf32.tf32.f32 "
        "{%0,%1,%2,%3},{%4,%5,%6,%7},{%8,%9},{%0,%1,%2,%3};"
        : "+f"(c[0]), "+f"(c[1]), "+f"(c[2]), "+f"(c[3])
        : "r"(a[0]), "r"(a[1]), "r"(a[2]), "r"(a[3]), "r"(b[0]), "r"(b[1]));
}

// ---------------- prep kernels ----------------
__global__ void k_cvt(const float* __restrict__ src, __nv_bfloat16* __restrict__ dst, size_t n) {
    size_t i = (size_t)blockIdx.x * blockDim.x + threadIdx.x;
    size_t stride = (size_t)gridDim.x * blockDim.x;
    for (; i < n; i += stride) dst[i] = __float2bfloat16_rn(src[i]);
}

// W (3H x H, gate-major rows g*H+h) -> bf16 with rows permuted to 3*h+g
__global__ void k_perm3(const float* __restrict__ src, __nv_bfloat16* __restrict__ dst) {
    int i = blockIdx.x * 256 + threadIdx.x;       // G3*HID elements
    int srow = i >> 10, k = i & 1023;
    int g = srow >> 10, h = srow & 1023;
    dst[((size_t)(3*h + g) << 10) | k] = __float2bfloat16_rn(src[i]);
}
// f32 permuted copy (for tf32 GRU GEMM)
__global__ void k_perm3f(const float* __restrict__ src, float* __restrict__ dst) {
    int i = blockIdx.x * 256 + threadIdx.x;
    int srow = i >> 10, k = i & 1023;
    int g = srow >> 10, h = srow & 1023;
    dst[((size_t)(3*h + g) << 10) | k] = src[i];
}
__global__ void k_perm3b(const float* __restrict__ src, float* __restrict__ dst) {
    int i = blockIdx.x * 256 + threadIdx.x;
    if (i < G3) { int g = i >> 10, h = i & 1023; dst[3*h + g] = src[i]; }
}

// W_proj (H x 2H) -> Wp1 bf16 (x-half), Wp2f f32 (mem-half)
__global__ void k_cvt_wproj(const float* __restrict__ Wproj) {
    int i = blockIdx.x * 256 + threadIdx.x;       // HID*HID
    int j = i >> 10, k = i & 1023;
    g_Wp1[i]  = __float2bfloat16_rn(Wproj[(size_t)j * 2048 + k]);
    g_Wp2f[i] = Wproj[(size_t)j * 2048 + 1024 + k];
}

// x rows (t*B+b): relu(emb_table[input[b,t]])
__global__ void k_emb(const int* __restrict__ input, const float* __restrict__ emb) {
    int idx = blockIdx.x * 256 + threadIdx.x;     // RN*HID
    int r = idx >> 10, h = idx & 1023;
    int t = r >> 5, b = r & 31;
    int tok = input[b * TN + t];
    float v = emb[(size_t)tok * HID + h];
    v = v > 0.f ? v : 0.f;
    g_xbf[idx] = __float2bfloat16_rn(v);
}

// ring init: S[k] = memory[31-k]  (mem[:,m] at step t lives in S[t+31-m])
__global__ void k_initS(const float* __restrict__ memory) {
    int idx = blockIdx.x * 256 + threadIdx.x;     // MEMN*SLOT = 1048576
    int k = idx >> 15, rest = idx & 32767;
    float v = memory[(size_t)(31 - k) * SLOT + rest];
    g_S[idx] = v;
    g_Sbf[idx] = __float2bfloat16_rn(v);
}

// ---------------- big GEMM (bf16): C(2048 x N) = A @ W^T + bias ----------------
__global__ __launch_bounds__(256) void k_gemm_big(
    const __nv_bfloat16* __restrict__ A, const __nv_bfloat16* __restrict__ Wt,
    const float* __restrict__ bias, float* __restrict__ C, int N)
{
    __shared__ __align__(16) __nv_bfloat16 As[128][40];
    __shared__ __align__(16) __nv_bfloat16 Bs[128][40];
    const int m0 = blockIdx.x * 128;
    const int n0 = blockIdx.y * 128;
    const int tid = threadIdx.x, lane = tid & 31, wid = tid >> 5;
    const int wm = (wid & 1) * 64;
    const int wn = (wid >> 1) * 32;

    float acc[4][4][4] = {};

    for (int k0 = 0; k0 < 1024; k0 += 32) {
        __syncthreads();
#pragma unroll
        for (int v = 0; v < 2; v++) {
            int task = tid + v * 256;
            int row = task >> 2, seg = task & 3;
            *(uint4*)&As[row][seg * 8] = *(const uint4*)&A [(size_t)(m0 + row) * 1024 + k0 + seg * 8];
            *(uint4*)&Bs[row][seg * 8] = *(const uint4*)&Wt[(size_t)(n0 + row) * 1024 + k0 + seg * 8];
        }
        __syncthreads();
#pragma unroll
        for (int kk = 0; kk < 32; kk += 16) {
            unsigned af[4][4], bfm[4][2];
#pragma unroll
            for (int mi = 0; mi < 4; mi++)
                ldmx4(af[mi], su32(&As[wm + mi * 16 + (lane & 15)][kk + (lane >> 4) * 8]));
#pragma unroll
            for (int ni = 0; ni < 4; ni++)
                ldmx2(bfm[ni], su32(&Bs[wn + ni * 8 + (lane & 7)][kk + ((lane >> 3) & 1) * 8]));
#pragma unroll
            for (int mi = 0; mi < 4; mi++)
#pragma unroll
                for (int ni = 0; ni < 4; ni++)
                    mma16816(acc[mi][ni], af[mi], bfm[ni]);
        }
    }
#pragma unroll
    for (int mi = 0; mi < 4; mi++)
#pragma unroll
        for (int ni = 0; ni < 4; ni++) {
            int row = m0 + wm + mi * 16 + (lane >> 2);
            int col = n0 + wn + ni * 8 + (lane & 3) * 2;
            float b0 = bias[col], b1 = bias[col + 1];
            C[(size_t)row * N + col]           = acc[mi][ni][0] + b0;
            C[(size_t)row * N + col + 1]       = acc[mi][ni][1] + b1;
            C[(size_t)(row + 8) * N + col]     = acc[mi][ni][2] + b0;
            C[(size_t)(row + 8) * N + col + 1] = acc[mi][ni][3] + b1;
        }
}

// ---------------- step kernel 1 (tf32): proj = mem0 @ Wp2^T + projA[t] ----------------
__global__ __launch_bounds__(128) void k_step_proj(int t)
{
    __shared__ uint32_t As[32][36];
    __shared__ uint32_t Bs[64][36];
    const int n0 = blockIdx.x * 64;
    const int tid = threadIdx.x, lane = tid & 31, wid = tid >> 5;
    const int wn = wid * 16;
    const float* A = g_S + (size_t)(t + 31) * SLOT;   // mem[:,0] (f32)
    const float* addend = g_projA + (size_t)t * SLOT;
    const int r4 = lane >> 2, c4 = lane & 3;

    float acc[2][2][4] = {};
    for (int k0 = 0; k0 < 1024; k0 += 32) {
        __syncthreads();
#pragma unroll
        for (int v = 0; v < 2; v++) {          // 32x32 f32 = 256 float4
            int task = tid + v * 128;
            int row = task >> 3, seg = task & 7;
            float4 x = *(const float4*)&A[(size_t)row * 1024 + k0 + seg * 4];
            uint32_t* d = &As[row][seg * 4];
            d[0] = f2tf(x.x); d[1] = f2tf(x.y); d[2] = f2tf(x.z); d[3] = f2tf(x.w);
        }
#pragma unroll
        for (int v = 0; v < 4; v++) {          // 64x32 f32 = 512 float4
            int task = tid + v * 128;
            int row = task >> 3, seg = task & 7;
            float4 x = *(const float4*)&g_Wp2f[(size_t)(n0 + row) * 1024 + k0 + seg * 4];
            uint32_t* d = &Bs[row][seg * 4];
            d[0] = f2tf(x.x); d[1] = f2tf(x.y); d[2] = f2tf(x.z); d[3] = f2tf(x.w);
        }
        __syncthreads();
#pragma unroll
        for (int kk = 0; kk < 32; kk += 8) {
            uint32_t af[2][4], bfr[2][2];
#pragma unroll
            for (int mi = 0; mi < 2; mi++) {
                af[mi][0] = As[mi * 16 + r4][kk + c4];
                af[mi][1] = As[mi * 16 + r4 + 8][kk + c4];
                af[mi][2] = As[mi * 16 + r4][kk + c4 + 4];
                af[mi][3] = As[mi * 16 + r4 + 8][kk + c4 + 4];
            }
#pragma unroll
            for (int ni = 0; ni < 2; ni++) {
                bfr[ni][0] = Bs[wn + ni * 8 + r4][kk + c4];
                bfr[ni][1] = Bs[wn + ni * 8 + r4][kk + c4 + 4];
            }
#pragma unroll
            for (int mi = 0; mi < 2; mi++)
#pragma unroll
                for (int ni = 0; ni < 2; ni++)
                    mma1688tf(acc[mi][ni], af[mi], bfr[ni]);
        }
    }
#pragma unroll
    for (int mi = 0; mi < 2; mi++)
#pragma unroll
        for (int ni = 0; ni < 2; ni++) {
            int row = mi * 16 + (lane >> 2);
            int col = n0 + wn + ni * 8 + (lane & 3) * 2;
            g_proj[row * HID + col]           = acc[mi][ni][0] + addend[row * HID + col];
            g_proj[row * HID + col + 1]       = acc[mi][ni][1] + addend[row * HID + col + 1];
            g_proj[(row + 8) * HID + col]     = acc[mi][ni][2] + addend[(row + 8) * HID + col];
            g_proj[(row + 8) * HID + col + 1] = acc[mi][ni][3] + addend[(row + 8) * HID + col + 1];
        }
}

// ---------------- step kernel 2: attention (one block per batch) ----------------
__global__ __launch_bounds__(1024) void k_attn(int t)
{
    const int b = blockIdx.x;
    const int tid = threadIdx.x, lane = tid & 31, wid = tid >> 5;
    __shared__ float dots[32];
    {   // warp `wid` handles memory slot m = wid
        const float* mrow = g_S + (size_t)(t + 31 - wid) * SLOT + b * HID;
        const float* prow = g_proj + b * HID;
        float s = 0.f;
#pragma unroll
        for (int j = 0; j < 32; j++) s += mrow[lane + j * 32] * prow[lane + j * 32];
#pragma unroll
        for (int o = 16; o; o >>= 1) s += __shfl_xor_sync(0xffffffffu, s, o);
        if (lane == 0) dots[wid] = s * 0.03125f;   // 1/sqrt(1024)
    }
    __syncthreads();
    if (wid == 0) {
        float d = dots[lane];
        float mx = d;
#pragma unroll
        for (int o = 16; o; o >>= 1) mx = fmaxf(mx, __shfl_xor_sync(0xffffffffu, mx, o));
        float e = expf(d - mx);
        float ss = e;
#pragma unroll
        for (int o = 16; o; o >>= 1) ss += __shfl_xor_sync(0xffffffffu, ss, o);
        dots[lane] = e / ss;
    }
    __syncthreads();
    float acc = 0.f;
#pragma unroll 8
    for (int m = 0; m < 32; m++)
        acc += dots[m] * g_S[(size_t)(t + 31 - m) * SLOT + b * HID + tid];
    g_sel[b * HID + tid] = acc;
}

// ---------------- step kernel 3 (tf32): gh = sel @ W_hh^T (interleaved), gates, write h ----------------
__global__ __launch_bounds__(128) void k_step_gru(int t)
{
    __shared__ uint32_t As[32][36];
    __shared__ uint32_t Bs[96][36];
    __shared__ float ghs[32][100];
    const int n0 = blockIdx.x * 96;     // interleaved gate columns
    const int h0 = blockIdx.x * 32;     // h range this block finalizes
    const int tid = threadIdx.x, lane = tid & 31, wid = tid >> 5;
    const int wn = wid * 24;
    const int r4 = lane >> 2, c4 = lane & 3;

    float acc[2][3][4] = {};
    for (int k0 = 0; k0 < 1024; k0 += 32) {
        __syncthreads();
#pragma unroll
        for (int v = 0; v < 2; v++) {          // sel 32x32 f32
            int task = tid + v * 128;
            int row = task >> 3, seg = task & 7;
            float4 x = *(const float4*)&g_sel[(size_t)row * 1024 + k0 + seg * 4];
            uint32_t* d = &As[row][seg * 4];
            d[0] = f2tf(x.x); d[1] = f2tf(x.y); d[2] = f2tf(x.z); d[3] = f2tf(x.w);
        }
#pragma unroll
        for (int v = 0; v < 6; v++) {          // Whh 96x32 f32
            int task = tid + v * 128;
            int row = task >> 3, seg = task & 7;
            float4 x = *(const float4*)&g_Whh3f[(size_t)(n0 + row) * 1024 + k0 + seg * 4];
            uint32_t* d = &Bs[row][seg * 4];
            d[0] = f2tf(x.x); d[1] = f2tf(x.y); d[2] = f2tf(x.z); d[3] = f2tf(x.w);
        }
        __syncthreads();
#pragma unroll
        for (int kk = 0; kk < 32; kk += 8) {
            uint32_t af[2][4], bfr[3][2];
#pragma unroll
            for (int mi = 0; mi < 2; mi++) {
                af[mi][0] = As[mi * 16 + r4][kk + c4];
                af[mi][1] = As[mi * 16 + r4 + 8][kk + c4];
                af[mi][2] = As[mi * 16 + r4][kk + c4 + 4];
                af[mi][3] = As[mi * 16 + r4 + 8][kk + c4 + 4];
            }
#pragma unroll
            for (int ni = 0; ni < 3; ni++) {
                bfr[ni][0] = Bs[wn + ni * 8 + r4][kk + c4];
                bfr[ni][1] = Bs[wn + ni * 8 + r4][kk + c4 + 4];
            }
#pragma unroll
            for (int mi = 0; mi < 2; mi++)
#pragma unroll
                for (int ni = 0; ni < 3; ni++)
                    mma1688tf(acc[mi][ni], af[mi], bfr[ni]);
        }
    }
#pragma unroll
    for (int mi = 0; mi < 2; mi++)
#pragma unroll
        for (int ni = 0; ni < 3; ni++) {
            int row = mi * 16 + (lane >> 2);
            int col = wn + ni * 8 + (lane & 3) * 2;   // local col within 96
            ghs[row][col]         = acc[mi][ni][0] + g_bhh3[n0 + col];
            ghs[row][col + 1]     = acc[mi][ni][1] + g_bhh3[n0 + col + 1];
            ghs[row + 8][col]     = acc[mi][ni][2] + g_bhh3[n0 + col];
            ghs[row + 8][col + 1] = acc[mi][ni][3] + g_bhh3[n0 + col + 1];
        }
    __syncthreads();
    // gates: 32 batches x 32 h-values
    for (int i = tid; i < 1024; i += 128) {
        int b = i >> 5, hh = i & 31;
        const float* gi = g_giAll + (size_t)(t * BAT + b) * G3 + n0 + 3 * hh;
        float hr = ghs[b][3 * hh + 0];
        float hz = ghs[b][3 * hh + 1];
        float hn = ghs[b][3 * hh + 2];
        float r = 1.f / (1.f + expf(-(gi[0] + hr)));
        float z = 1.f / (1.f + expf(-(gi[1] + hz)));
        float n = tanhf(gi[2] + r * hn);
        float sv = g_sel[b * HID + h0 + hh];
        float hv = (1.f - z) * n + z * sv;
        size_t o = (size_t)(MEMN + t) * SLOT + b * HID + h0 + hh;
        g_S[o] = hv;
        g_Sbf[o] = __float2bfloat16_rn(hv);
    }
}

// ---------------- log-softmax ----------------
__global__ __launch_bounds__(256) void k_lse()
{
    const int r = blockIdx.x;
    const float* row = g_logits + (size_t)r * VOC;
    __shared__ float red[8];
    __shared__ float bc;
    int tid = threadIdx.x, lane = tid & 31, wid = tid >> 5;
    float m = -1e30f;
    for (int i = tid; i < VOC; i += 256) m = fmaxf(m, row[i]);
#pragma unroll
    for (int o = 16; o; o >>= 1) m = fmaxf(m, __shfl_xor_sync(0xffffffffu, m, o));
    if (lane == 0) red[wid] = m;
    __syncthreads();
    if (tid == 0) {
        float mm = red[0];
        for (int w = 1; w < 8; w++) mm = fmaxf(mm, red[w]);
        bc = mm;
    }
    __syncthreads();
    float M = bc;
    float s = 0.f;
    for (int i = tid; i < VOC; i += 256) s += expf(row[i] - M);
#pragma unroll
    for (int o = 16; o; o >>= 1) s += __shfl_xor_sync(0xffffffffu, s, o);
    if (lane == 0) red[wid] = s;
    __syncthreads();
    if (tid == 0) {
        float ss = 0.f;
        for (int w = 0; w < 8; w++) ss += red[w];
        g_lse[r] = M + logf(ss);
    }
}

__global__ __launch_bounds__(256) void k_out(float* __restrict__ out)
{
    const int r = blockIdx.x;            // r = t*BAT + b
    const int t = r >> 5, b = r & 31;
    const float l = g_lse[r];
    const float4* src = (const float4*)(g_logits + (size_t)r * VOC);
    float4* dst = (float4*)(out + ((size_t)b * TN + t) * VOC);
    for (int i = threadIdx.x; i < VOC / 4; i += 256) {
        float4 v = src[i];
        v.x -= l; v.y -= l; v.z -= l; v.w -= l;
        dst[i] = v;
    }
}

// final memory output (MEM, B, H): out2[m][b][h] = S[95 - m][b][h]
__global__ void k_outmem(float* __restrict__ out2)
{
    int idx = blockIdx.x * 256 + threadIdx.x;   // MEM*SLOT/4 float4 elements
    int m = idx / (SLOT / 4);
    int rest = idx % (SLOT / 4);
    const float4* src = (const float4*)(g_S + (size_t)(MEMN + TN - 1 - m) * SLOT);
    float4* dst = (float4*)(out2 + (size_t)m * SLOT);
    dst[rest] = src[rest];
}

// ---------------- launch ----------------
extern "C" void kernel_launch(void* const* d_in, const int* in_sizes, int n_in,
                              void* d_out, int out_size)
{
    const int*   input  = (const int*)  d_in[0];
    const float* memory = (const float*)d_in[1];
    const float* emb    = (const float*)d_in[2];
    const float* W_proj = (const float*)d_in[3];
    const float* b_proj = (const float*)d_in[4];
    const float* W_ih   = (const float*)d_in[5];
    const float* W_hh   = (const float*)d_in[6];
    const float* b_ih   = (const float*)d_in[7];
    const float* b_hh   = (const float*)d_in[8];
    const float* W_out  = (const float*)d_in[9];
    const float* b_out  = (const float*)d_in[10];
    float* out = (float*)d_out;

    void *pWout, *pWih3, *pWhh3f, *pbih3, *pbhh3, *pWp1, *pxbf, *pgi, *pprojA, *pSbf, *plogits;
    cudaGetSymbolAddress(&pWout, g_Wout);
    cudaGetSymbolAddress(&pWih3, g_Wih3);
    cudaGetSymbolAddress(&pWhh3f, g_Whh3f);
    cudaGetSymbolAddress(&pbih3, g_bih3);
    cudaGetSymbolAddress(&pbhh3, g_bhh3);
    cudaGetSymbolAddress(&pWp1,  g_Wp1);
    cudaGetSymbolAddress(&pxbf,  g_xbf);
    cudaGetSymbolAddress(&pgi,   g_giAll);
    cudaGetSymbolAddress(&pprojA,g_projA);
    cudaGetSymbolAddress(&pSbf,  g_Sbf);
    cudaGetSymbolAddress(&plogits, g_logits);

    // ---- prep ----
    k_cvt<<<4096, 256>>>(W_out, (__nv_bfloat16*)pWout, (size_t)VOC * HID);
    k_perm3<<<(G3 * HID) / 256, 256>>>(W_ih, (__nv_bfloat16*)pWih3);
    k_perm3f<<<(G3 * HID) / 256, 256>>>(W_hh, (float*)pWhh3f);
    k_perm3b<<<12, 256>>>(b_ih, (float*)pbih3);
    k_perm3b<<<12, 256>>>(b_hh, (float*)pbhh3);
    k_cvt_wproj<<<(HID * HID) / 256, 256>>>(W_proj);
    k_emb<<<(RN * HID) / 256, 256>>>(input, emb);
    k_initS<<<(MEMN * SLOT) / 256, 256>>>(memory);

    k_gemm_big<<<dim3(16, 24), 256>>>((const __nv_bfloat16*)pxbf, (const __nv_bfloat16*)pWih3,
                                      (const float*)pbih3, (float*)pgi, G3);
    k_gemm_big<<<dim3(16, 8), 256>>>((const __nv_bfloat16*)pxbf, (const __nv_bfloat16*)pWp1,
                                     b_proj, (float*)pprojA, HID);

    // ---- sequential recurrence ----
    for (int t = 0; t < TN; t++) {
        k_step_proj<<<16, 128>>>(t);
        k_attn<<<32, 1024>>>(t);
        k_step_gru<<<32, 128>>>(t);
    }

    // ---- vocab projection + log-softmax ----
    k_gemm_big<<<dim3(16, 250), 256>>>((const __nv_bfloat16*)pSbf + (size_t)MEMN * SLOT,
                                       (const __nv_bfloat16*)pWout, b_out, (float*)plogits, VOC);
    k_lse<<<RN, 256>>>();
    k_out<<<RN, 256>>>(out);
    k_outmem<<<(MEMN * SLOT / 4) / 256, 256>>>(out + (size_t)BAT * TN * VOC);
}

// round 9
// speedup vs baseline: 2.5896x; 2.5896x over previous
#include <cuda_runtime.h>
#include <cuda_bf16.h>
#include <math.h>
#include <stdint.h>

#define HID 1024
#define VOC 32000
#define MEMN 32
#define BAT 32
#define TN 64
#define RN (TN*BAT)      // 2048
#define G3 (3*HID)       // 3072
#define SLOT (BAT*HID)   // 32768
#define NBLK 128

// ---------------- device scratch (static, no allocs) ----------------
__device__ __align__(16) __nv_bfloat16 g_Wout[(size_t)VOC*HID];
__device__ __align__(16) __nv_bfloat16 g_Wih3[(size_t)G3*HID];   // bf16, rows permuted 3*h+g
__device__ __align__(16) float g_Whh3f[(size_t)G3*HID];          // f32, rows permuted 3*h+g
__device__ __align__(16) float g_bih3[G3];
__device__ __align__(16) float g_bhh3[G3];
__device__ __align__(16) __nv_bfloat16 g_Wp1[(size_t)HID*HID];   // bf16 x-half of W_proj
__device__ __align__(16) float g_Wp2f[(size_t)HID*HID];          // f32 mem-half of W_proj
__device__ __align__(16) __nv_bfloat16 g_xbf[(size_t)RN*HID];    // relu(emb), rows (t*B+b)
__device__ __align__(16) float         g_S  [(size_t)(MEMN+TN)*SLOT];  // state ring f32
__device__ __align__(16) __nv_bfloat16 g_Sbf[(size_t)(MEMN+TN)*SLOT];  // state ring bf16
__device__ __align__(16) float g_giAll[(size_t)RN*G3];           // x@W_ih^T+b_ih (perm cols)
__device__ __align__(16) float g_projA[(size_t)RN*HID];          // x@Wp1^T+b_proj
__device__ __align__(16) float g_proj[(size_t)BAT*HID];
__device__ __align__(16) float g_sel[(size_t)BAT*HID];
__device__ __align__(16) float g_logits[(size_t)RN*VOC];
__device__ float g_lse[RN];
__device__ unsigned g_barCnt;

// ---------------- mma helpers ----------------
__device__ __forceinline__ unsigned su32(const void* p) {
    return (unsigned)__cvta_generic_to_shared(p);
}
__device__ __forceinline__ void ldmx4(unsigned* r, unsigned a) {
    asm volatile("ldmatrix.sync.aligned.m8n8.x4.shared.b16 {%0,%1,%2,%3},[%4];"
                 : "=r"(r[0]), "=r"(r[1]), "=r"(r[2]), "=r"(r[3]) : "r"(a));
}
__device__ __forceinline__ void ldmx2(unsigned* r, unsigned a) {
    asm volatile("ldmatrix.sync.aligned.m8n8.x2.shared.b16 {%0,%1},[%2];"
                 : "=r"(r[0]), "=r"(r[1]) : "r"(a));
}
__device__ __forceinline__ void mma16816(float* c, const unsigned* a, const unsigned* b) {
    asm volatile(
        "mma.sync.aligned.m16n8k16.row.col.f32.bf16.bf16.f32 "
        "{%0,%1,%2,%3},{%4,%5,%6,%7},{%8,%9},{%0,%1,%2,%3};"
        : "+f"(c[0]), "+f"(c[1]), "+f"(c[2]), "+f"(c[3])
        : "r"(a[0]), "r"(a[1]), "r"(a[2]), "r"(a[3]), "r"(b[0]), "r"(b[1]));
}
__device__ __forceinline__ uint32_t f2tf(float f) {
    uint32_t r;
    asm("cvt.rna.tf32.f32 %0, %1;" : "=r"(r) : "f"(f));
    return r;
}
__device__ __forceinline__ void mma1688tf(float* c, const uint32_t* a, const uint32_t* b) {
    asm volatile(
        "mma.sync.aligned.m16n8k8.row.col.f32.tf32.tf32.f32 "
        "{%0,%1,%2,%3},{%4,%5,%6,%7},{%8,%9},{%0,%1,%2,%3};"
        : "+f"(c[0]), "+f"(c[1]), "+f"(c[2]), "+f"(c[3])
        : "r"(a[0]), "r"(a[1]), "r"(a[2]), "r"(a[3]), "r"(b[0]), "r"(b[1]));
}

// ---------------- grid barrier (monotonic counter) ----------------
__device__ __forceinline__ unsigned ldacq(const unsigned* p) {
    unsigned v;
    asm volatile("ld.acquire.gpu.global.u32 %0, [%1];" : "=r"(v) : "l"(p));
    return v;
}
__device__ __forceinline__ void gsync(unsigned &target) {
    __syncthreads();
    if (threadIdx.x == 0) {
        __threadfence();
        atomicAdd(&g_barCnt, 1u);
        target += NBLK;
        while (ldacq(&g_barCnt) < target) { }
    }
    __syncthreads();
}

// ---------------- prep kernels ----------------
__global__ void k_cvtWout(const float* __restrict__ W_out) {
    size_t i = (size_t)blockIdx.x * 256 + threadIdx.x;   // VOC*HID
    g_Wout[i] = __float2bfloat16_rn(W_out[i]);
}
__global__ void k_permWih(const float* __restrict__ W_ih) {
    int i = blockIdx.x * 256 + threadIdx.x;              // G3*HID
    int srow = i >> 10, k = i & 1023;
    int g = srow >> 10, h = srow & 1023;
    g_Wih3[((size_t)(3*h + g) << 10) | k] = __float2bfloat16_rn(W_ih[i]);
}
__global__ void k_prepW(const float* __restrict__ W_hh, const float* __restrict__ W_proj,
                        const float* __restrict__ b_ih, const float* __restrict__ b_hh) {
    int blk = blockIdx.x, tid = threadIdx.x;
    if (blk < 12288) {                      // Whh perm f32
        int i = blk * 256 + tid;
        int srow = i >> 10, k = i & 1023;
        int g = srow >> 10, h = srow & 1023;
        g_Whh3f[((size_t)(3*h + g) << 10) | k] = W_hh[i];
    } else if (blk < 16384) {               // W_proj split
        int i = (blk - 12288) * 256 + tid;
        int j = i >> 10, k = i & 1023;
        g_Wp1[i]  = __float2bfloat16_rn(W_proj[(size_t)j * 2048 + k]);
        g_Wp2f[i] = W_proj[(size_t)j * 2048 + 1024 + k];
    } else {                                // biases permuted
        int i = (blk - 16384) * 256 + tid;
        if (i < G3) {
            int g = i >> 10, h = i & 1023;
            g_bih3[3*h + g] = b_ih[i];
            g_bhh3[3*h + g] = b_hh[i];
        }
    }
}
__global__ void k_embS(const int* __restrict__ input, const float* __restrict__ emb,
                       const float* __restrict__ memory) {
    int blk = blockIdx.x, tid = threadIdx.x;
    if (blk == 0 && tid == 0) g_barCnt = 0;
    if (blk < 8192) {                       // relu(emb[input]) rows (t*B+b)
        int idx = blk * 256 + tid;
        int r = idx >> 10, h = idx & 1023;
        int t = r >> 5, b = r & 31;
        int tok = input[b * TN + t];
        float v = emb[(size_t)tok * HID + h];
        g_xbf[idx] = __float2bfloat16_rn(v > 0.f ? v : 0.f);
    } else {                                // ring init S[k] = memory[31-k]
        int idx = (blk - 8192) * 256 + tid;
        int k = idx >> 15, rest = idx & 32767;
        float v = memory[(size_t)(31 - k) * SLOT + rest];
        g_S[idx] = v;
        g_Sbf[idx] = __float2bfloat16_rn(v);
    }
}

// ---------------- bf16 128x128 GEMM body (device) ----------------
__device__ __forceinline__ void gemm128_body(
    const __nv_bfloat16* __restrict__ A, const __nv_bfloat16* __restrict__ Wt,
    const float* __restrict__ bias, float* __restrict__ C, int N, int m0, int n0,
    __nv_bfloat16 (*As)[40], __nv_bfloat16 (*Bs)[40])
{
    const int tid = threadIdx.x, lane = tid & 31, wid = tid >> 5;
    const int wm = (wid & 1) * 64;
    const int wn = (wid >> 1) * 32;
    float acc[4][4][4] = {};
    for (int k0 = 0; k0 < 1024; k0 += 32) {
        __syncthreads();
#pragma unroll
        for (int v = 0; v < 2; v++) {
            int task = tid + v * 256;
            int row = task >> 2, seg = task & 3;
            *(uint4*)&As[row][seg * 8] = *(const uint4*)&A [(size_t)(m0 + row) * 1024 + k0 + seg * 8];
            *(uint4*)&Bs[row][seg * 8] = *(const uint4*)&Wt[(size_t)(n0 + row) * 1024 + k0 + seg * 8];
        }
        __syncthreads();
#pragma unroll
        for (int kk = 0; kk < 32; kk += 16) {
            unsigned af[4][4], bfm[4][2];
#pragma unroll
            for (int mi = 0; mi < 4; mi++)
                ldmx4(af[mi], su32(&As[wm + mi * 16 + (lane & 15)][kk + (lane >> 4) * 8]));
#pragma unroll
            for (int ni = 0; ni < 4; ni++)
                ldmx2(bfm[ni], su32(&Bs[wn + ni * 8 + (lane & 7)][kk + ((lane >> 3) & 1) * 8]));
#pragma unroll
            for (int mi = 0; mi < 4; mi++)
#pragma unroll
                for (int ni = 0; ni < 4; ni++)
                    mma16816(acc[mi][ni], af[mi], bfm[ni]);
        }
    }
#pragma unroll
    for (int mi = 0; mi < 4; mi++)
#pragma unroll
        for (int ni = 0; ni < 4; ni++) {
            int row = m0 + wm + mi * 16 + (lane >> 2);
            int col = n0 + wn + ni * 8 + (lane & 3) * 2;
            float b0 = bias[col], b1 = bias[col + 1];
            C[(size_t)row * N + col]           = acc[mi][ni][0] + b0;
            C[(size_t)row * N + col + 1]       = acc[mi][ni][1] + b1;
            C[(size_t)(row + 8) * N + col]     = acc[mi][ni][2] + b0;
            C[(size_t)(row + 8) * N + col + 1] = acc[mi][ni][3] + b1;
        }
}

// gi (y<24) + projA (y>=24) in one launch
__global__ __launch_bounds__(256) void k_gemm_all(const float* __restrict__ b_proj)
{
    __shared__ __align__(16) __nv_bfloat16 As[128][40];
    __shared__ __align__(16) __nv_bfloat16 Bs[128][40];
    int m0 = blockIdx.x * 128;
    if (blockIdx.y < 24)
        gemm128_body(g_xbf, g_Wih3, g_bih3, g_giAll, G3, m0, blockIdx.y * 128, As, Bs);
    else
        gemm128_body(g_xbf, g_Wp1, b_proj, g_projA, HID, m0, (blockIdx.y - 24) * 128, As, Bs);
}
// vocab projection
__global__ __launch_bounds__(256) void k_gemm_voc(const float* __restrict__ b_out)
{
    __shared__ __align__(16) __nv_bfloat16 As[128][40];
    __shared__ __align__(16) __nv_bfloat16 Bs[128][40];
    gemm128_body(g_Sbf + (size_t)MEMN * SLOT, g_Wout, b_out, g_logits, VOC,
                 blockIdx.x * 128, blockIdx.y * 128, As, Bs);
}

// ---------------- persistent recurrence kernel ----------------
// smem: wWp2[8][1028] | wWhh[24][1028] | As[32][132] | red[8*32*24] | dots[32]
#define SM_RECUR ((8*1028 + 24*1028 + 32*132) * 4 + 8*32*24*4 + 32*4)

__global__ __launch_bounds__(256, 1) void k_recur()
{
    extern __shared__ __align__(16) char sm_raw[];
    uint32_t* wWp2 = (uint32_t*)sm_raw;            // [8][1028]
    uint32_t* wWhh = wWp2 + 8 * 1028;              // [24][1028]
    uint32_t* As   = wWhh + 24 * 1028;             // [32][132]
    float*    red  = (float*)(As + 32 * 132);      // [8][32][24]
    float*    dots = red + 8 * 32 * 24;            // [32]

    const int tid = threadIdx.x, blk = blockIdx.x;
    const int lane = tid & 31, wid = tid >> 5;
    const int r4 = lane >> 2, c4 = lane & 3;
    const int n0p = blk * 8, n0g = blk * 24, h0 = blk * 8;

    // cache weight slices as tf32 in smem (once)
    for (int i = tid; i < 8 * 1024; i += 256) {
        int r = i >> 10, k = i & 1023;
        wWp2[r * 1028 + k] = f2tf(g_Wp2f[(size_t)(n0p + r) * 1024 + k]);
    }
    for (int i = tid; i < 24 * 1024; i += 256) {
        int r = i >> 10, k = i & 1023;
        wWhh[r * 1028 + k] = f2tf(g_Whh3f[(size_t)(n0g + r) * 1024 + k]);
    }
    __syncthreads();

    unsigned target = 0;

    for (int t = 0; t < TN; t++) {
        // ===== phase P: proj(32x1024) = mem0 @ Wp2^T + projA[t], 8 cols/block =====
        {
            const float* Ap = g_S + (size_t)(t + 31) * SLOT;
            float accP[2][4] = {};
            for (int c = 0; c < 8; c++) {
#pragma unroll
                for (int v = 0; v < 4; v++) {
                    int idx = tid + v * 256, row = idx >> 5, seg = idx & 31;
                    float4 x = __ldcg((const float4*)&Ap[(size_t)row * 1024 + c * 128 + seg * 4]);
                    uint4 u;
                    u.x = f2tf(x.x); u.y = f2tf(x.y); u.z = f2tf(x.z); u.w = f2tf(x.w);
                    *(uint4*)&As[row * 132 + seg * 4] = u;
                }
                __syncthreads();
                int kb = wid * 16;
#pragma unroll
                for (int ks = 0; ks < 16; ks += 8) {
                    int kl = kb + ks, kg = c * 128 + kl;
                    uint32_t af[2][4], bf2[2];
#pragma unroll
                    for (int mi = 0; mi < 2; mi++) {
                        af[mi][0] = As[(mi * 16 + r4) * 132 + kl + c4];
                        af[mi][1] = As[(mi * 16 + r4 + 8) * 132 + kl + c4];
                        af[mi][2] = As[(mi * 16 + r4) * 132 + kl + c4 + 4];
                        af[mi][3] = As[(mi * 16 + r4 + 8) * 132 + kl + c4 + 4];
                    }
                    bf2[0] = wWp2[r4 * 1028 + kg + c4];
                    bf2[1] = wWp2[r4 * 1028 + kg + c4 + 4];
                    mma1688tf(accP[0], af[0], bf2);
                    mma1688tf(accP[1], af[1], bf2);
                }
                __syncthreads();
            }
            {   // cross-warp partials
                float* pr = red + wid * 256;
                int cb = (lane & 3) * 2;
#pragma unroll
                for (int mi = 0; mi < 2; mi++) {
                    int rr = mi * 16 + r4;
                    pr[rr * 8 + cb]           = accP[mi][0];
                    pr[rr * 8 + cb + 1]       = accP[mi][1];
                    pr[(rr + 8) * 8 + cb]     = accP[mi][2];
                    pr[(rr + 8) * 8 + cb + 1] = accP[mi][3];
                }
            }
            __syncthreads();
            {
                int row = tid >> 3, col = tid & 7;
                float s = 0.f;
#pragma unroll
                for (int w = 0; w < 8; w++) s += red[w * 256 + row * 8 + col];
                s += g_projA[(size_t)t * SLOT + row * 1024 + n0p + col];
                g_proj[row * 1024 + n0p + col] = s;
            }
        }
        gsync(target);

        // ===== phase A: attention, blocks 0..31 (one per batch) =====
        if (blk < BAT) {
            const int b = blk;
            float* projS = (float*)As;
#pragma unroll
            for (int p = 0; p < 4; p++)
                projS[tid + p * 256] = __ldcg(&g_proj[b * HID + tid + p * 256]);
            __syncthreads();
#pragma unroll
            for (int s = 0; s < 4; s++) {
                int m = wid * 4 + s;
                const float* mrow = g_S + (size_t)(t + 31 - m) * SLOT + b * HID;
                float sum = 0.f;
#pragma unroll
                for (int j = 0; j < 32; j++)
                    sum += __ldcg(&mrow[lane + 32 * j]) * projS[lane + 32 * j];
#pragma unroll
                for (int o = 16; o; o >>= 1) sum += __shfl_xor_sync(~0u, sum, o);
                if (lane == 0) dots[m] = sum * 0.03125f;   // 1/sqrt(1024)
            }
            __syncthreads();
            if (wid == 0) {
                float d = dots[lane], mx = d;
#pragma unroll
                for (int o = 16; o; o >>= 1) mx = fmaxf(mx, __shfl_xor_sync(~0u, mx, o));
                float e = expf(d - mx), ss = e;
#pragma unroll
                for (int o = 16; o; o >>= 1) ss += __shfl_xor_sync(~0u, ss, o);
                dots[lane] = e / ss;
            }
            __syncthreads();
#pragma unroll
            for (int p = 0; p < 4; p++) {
                int h = tid + p * 256;
                float acc = 0.f;
#pragma unroll
                for (int m = 0; m < 32; m++)
                    acc += dots[m] * __ldcg(&g_S[(size_t)(t + 31 - m) * SLOT + b * HID + h]);
                g_sel[b * HID + h] = acc;
            }
        }
        gsync(target);

        // ===== phase G: gh = sel @ Whh^T (24 gate-cols/block), gates, write h =====
        {
            float accG[2][3][4] = {};
            for (int c = 0; c < 8; c++) {
#pragma unroll
                for (int v = 0; v < 4; v++) {
                    int idx = tid + v * 256, row = idx >> 5, seg = idx & 31;
                    float4 x = __ldcg((const float4*)&g_sel[(size_t)row * 1024 + c * 128 + seg * 4]);
                    uint4 u;
                    u.x = f2tf(x.x); u.y = f2tf(x.y); u.z = f2tf(x.z); u.w = f2tf(x.w);
                    *(uint4*)&As[row * 132 + seg * 4] = u;
                }
                __syncthreads();
                int kb = wid * 16;
#pragma unroll
                for (int ks = 0; ks < 16; ks += 8) {
                    int kl = kb + ks, kg = c * 128 + kl;
                    uint32_t af[2][4];
#pragma unroll
                    for (int mi = 0; mi < 2; mi++) {
                        af[mi][0] = As[(mi * 16 + r4) * 132 + kl + c4];
                        af[mi][1] = As[(mi * 16 + r4 + 8) * 132 + kl + c4];
                        af[mi][2] = As[(mi * 16 + r4) * 132 + kl + c4 + 4];
                        af[mi][3] = As[(mi * 16 + r4 + 8) * 132 + kl + c4 + 4];
                    }
#pragma unroll
                    for (int ni = 0; ni < 3; ni++) {
                        uint32_t bf2[2] = { wWhh[(ni * 8 + r4) * 1028 + kg + c4],
                                            wWhh[(ni * 8 + r4) * 1028 + kg + c4 + 4] };
                        mma1688tf(accG[0][ni], af[0], bf2);
                        mma1688tf(accG[1][ni], af[1], bf2);
                    }
                }
                __syncthreads();
            }
            {
                float* pr = red + wid * 768;
                int cb = (lane & 3) * 2;
#pragma unroll
                for (int mi = 0; mi < 2; mi++)
#pragma unroll
                    for (int ni = 0; ni < 3; ni++) {
                        int rr = mi * 16 + r4, cc = ni * 8 + cb;
                        pr[rr * 24 + cc]           = accG[mi][ni][0];
                        pr[rr * 24 + cc + 1]       = accG[mi][ni][1];
                        pr[(rr + 8) * 24 + cc]     = accG[mi][ni][2];
                        pr[(rr + 8) * 24 + cc + 1] = accG[mi][ni][3];
                    }
            }
            __syncthreads();
            {
                int b = tid >> 3, hh = tid & 7;
                float gg[3];
#pragma unroll
                for (int g = 0; g < 3; g++) {
                    float s = g_bhh3[n0g + 3 * hh + g];
#pragma unroll
                    for (int w = 0; w < 8; w++) s += red[w * 768 + b * 24 + 3 * hh + g];
                    gg[g] = s;
                }
                const float* gi = g_giAll + (size_t)(t * BAT + b) * G3 + n0g + 3 * hh;
                float r = 1.f / (1.f + expf(-(gi[0] + gg[0])));
                float z = 1.f / (1.f + expf(-(gi[1] + gg[1])));
                float n = tanhf(gi[2] + r * gg[2]);
                float sv = __ldcg(&g_sel[b * HID + h0 + hh]);
                float hv = (1.f - z) * n + z * sv;
                size_t o = (size_t)(MEMN + t) * SLOT + b * HID + h0 + hh;
                g_S[o] = hv;
                g_Sbf[o] = __float2bfloat16_rn(hv);
            }
        }
        gsync(target);
    }
}

// ---------------- log-softmax + outputs ----------------
__global__ __launch_bounds__(256) void k_lse()
{
    const int r = blockIdx.x;
    const float* row = g_logits + (size_t)r * VOC;
    __shared__ float red[8];
    __shared__ float bc;
    int tid = threadIdx.x, lane = tid & 31, wid = tid >> 5;
    float m = -1e30f;
    for (int i = tid; i < VOC; i += 256) m = fmaxf(m, row[i]);
#pragma unroll
    for (int o = 16; o; o >>= 1) m = fmaxf(m, __shfl_xor_sync(~0u, m, o));
    if (lane == 0) red[wid] = m;
    __syncthreads();
    if (tid == 0) {
        float mm = red[0];
        for (int w = 1; w < 8; w++) mm = fmaxf(mm, red[w]);
        bc = mm;
    }
    __syncthreads();
    float M = bc;
    float s = 0.f;
    for (int i = tid; i < VOC; i += 256) s += expf(row[i] - M);
#pragma unroll
    for (int o = 16; o; o >>= 1) s += __shfl_xor_sync(~0u, s, o);
    if (lane == 0) red[wid] = s;
    __syncthreads();
    if (tid == 0) {
        float ss = 0.f;
        for (int w = 0; w < 8; w++) ss += red[w];
        g_lse[r] = M + logf(ss);
    }
}

__global__ __launch_bounds__(256) void k_out(float* __restrict__ out)
{
    const int r = blockIdx.x;            // r = t*BAT + b
    const int t = r >> 5, b = r & 31;
    const float l = g_lse[r];
    const float4* src = (const float4*)(g_logits + (size_t)r * VOC);
    float4* dst = (float4*)(out + ((size_t)b * TN + t) * VOC);
    for (int i = threadIdx.x; i < VOC / 4; i += 256) {
        float4 v = src[i];
        v.x -= l; v.y -= l; v.z -= l; v.w -= l;
        dst[i] = v;
    }
}

// out2 (MEM,B,H): out2[m][b][h] = S[95-m][b][h]
__global__ void k_outmem(float* __restrict__ out2)
{
    int idx = blockIdx.x * 256 + threadIdx.x;
    int m = idx / (SLOT / 4);
    int rest = idx % (SLOT / 4);
    const float4* src = (const float4*)(g_S + (size_t)(MEMN + TN - 1 - m) * SLOT);
    float4* dst = (float4*)(out2 + (size_t)m * SLOT);
    dst[rest] = src[rest];
}

// ---------------- launch ----------------
extern "C" void kernel_launch(void* const* d_in, const int* in_sizes, int n_in,
                              void* d_out, int out_size)
{
    const int*   input  = (const int*)  d_in[0];
    const float* memory = (const float*)d_in[1];
    const float* emb    = (const float*)d_in[2];
    const float* W_proj = (const float*)d_in[3];
    const float* b_proj = (const float*)d_in[4];
    const float* W_ih   = (const float*)d_in[5];
    const float* W_hh   = (const float*)d_in[6];
    const float* b_ih   = (const float*)d_in[7];
    const float* b_hh   = (const float*)d_in[8];
    const float* W_out  = (const float*)d_in[9];
    const float* b_out  = (const float*)d_in[10];
    float* out = (float*)d_out;

    cudaFuncSetAttribute(k_recur, cudaFuncAttributeMaxDynamicSharedMemorySize, SM_RECUR);

    k_cvtWout<<<(int)(((size_t)VOC * HID) / 256), 256>>>(W_out);            // 1
    k_permWih<<<(G3 * HID) / 256, 256>>>(W_ih);                             // 2
    k_prepW<<<16384 + 12, 256>>>(W_hh, W_proj, b_ih, b_hh);                 // 3
    k_embS<<<8192 + 4096, 256>>>(input, emb, memory);                       // 4
    k_gemm_all<<<dim3(16, 32), 256>>>(b_proj);                              // 5
    k_recur<<<NBLK, 256, SM_RECUR>>>();                                     // 6 (ncu target)
    k_gemm_voc<<<dim3(16, 250), 256>>>(b_out);                              // 7
    k_lse<<<RN, 256>>>();
    k_out<<<RN, 256>>>(out);
    k_outmem<<<(MEMN * SLOT / 4) / 256, 256>>>(out + (size_t)BAT * TN * VOC);
}

// round 11
// speedup vs baseline: 2.8432x; 1.0980x over previous
#include <cuda_runtime.h>
#include <cuda_bf16.h>
#include <math.h>
#include <stdint.h>

#define HID 1024
#define VOC 32000
#define MEMN 32
#define BAT 32
#define TN 64
#define RN (TN*BAT)      // 2048
#define G3 (3*HID)       // 3072
#define SLOT (BAT*HID)   // 32768
#define NBLK 128
#define WOUTB 128000     // (VOC*HID)/256 blocks for W_out conversion

// ---------------- device scratch (static, no allocs) ----------------
__device__ __align__(16) __nv_bfloat16 g_Wout[(size_t)VOC*HID];
__device__ __align__(16) __nv_bfloat16 g_Wih3[(size_t)G3*HID];   // bf16, rows permuted 3*h+g
__device__ __align__(16) float g_Whh3f[(size_t)G3*HID];          // f32, rows permuted 3*h+g
__device__ __align__(16) float g_bih3[G3];
__device__ __align__(16) float g_bhh3[G3];
__device__ __align__(16) __nv_bfloat16 g_Wp1[(size_t)HID*HID];   // bf16 x-half of W_proj
__device__ __align__(16) float g_Wp2f[(size_t)HID*HID];          // f32 mem-half of W_proj
__device__ __align__(16) __nv_bfloat16 g_xbf[(size_t)RN*HID];    // relu(emb), rows (t*B+b)
__device__ __align__(16) float         g_S  [(size_t)(MEMN+TN)*SLOT];  // state ring f32
__device__ __align__(16) __nv_bfloat16 g_Sbf[(size_t)(MEMN+TN)*SLOT];  // state ring bf16
__device__ __align__(16) float g_giAll[(size_t)RN*G3];           // x@W_ih^T+b_ih (perm cols)
__device__ __align__(16) float g_projA[(size_t)RN*HID];          // x@Wp1^T+b_proj
__device__ __align__(16) float g_proj[(size_t)BAT*HID];
__device__ __align__(16) float g_sel[(size_t)BAT*HID];
__device__ __align__(16) float g_logits[(size_t)RN*VOC];
__device__ float g_lse[RN];
__device__ unsigned g_barCnt;

// ---------------- helpers ----------------
__device__ __forceinline__ unsigned su32(const void* p) {
    return (unsigned)__cvta_generic_to_shared(p);
}
__device__ __forceinline__ void cpa16(void* smem_dst, const void* gsrc) {
    asm volatile("cp.async.cg.shared.global [%0], [%1], 16;"
                 :: "r"(su32(smem_dst)), "l"(gsrc));
}
#define CPA_COMMIT() asm volatile("cp.async.commit_group;")
#define CPA_WAIT0()  asm volatile("cp.async.wait_group 0;" ::: "memory")

__device__ __forceinline__ void ldmx4(unsigned* r, unsigned a) {
    asm volatile("ldmatrix.sync.aligned.m8n8.x4.shared.b16 {%0,%1,%2,%3},[%4];"
                 : "=r"(r[0]), "=r"(r[1]), "=r"(r[2]), "=r"(r[3]) : "r"(a));
}
__device__ __forceinline__ void ldmx2(unsigned* r, unsigned a) {
    asm volatile("ldmatrix.sync.aligned.m8n8.x2.shared.b16 {%0,%1},[%2];"
                 : "=r"(r[0]), "=r"(r[1]) : "r"(a));
}
__device__ __forceinline__ void mma16816(float* c, const unsigned* a, const unsigned* b) {
    asm volatile(
        "mma.sync.aligned.m16n8k16.row.col.f32.bf16.bf16.f32 "
        "{%0,%1,%2,%3},{%4,%5,%6,%7},{%8,%9},{%0,%1,%2,%3};"
        : "+f"(c[0]), "+f"(c[1]), "+f"(c[2]), "+f"(c[3])
        : "r"(a[0]), "r"(a[1]), "r"(a[2]), "r"(a[3]), "r"(b[0]), "r"(b[1]));
}
__device__ __forceinline__ uint32_t f2tf(float f) {
    uint32_t r;
    asm("cvt.rna.tf32.f32 %0, %1;" : "=r"(r) : "f"(f));
    return r;
}
__device__ __forceinline__ void mma1688tf(float* c, const uint32_t* a, const uint32_t* b) {
    asm volatile(
        "mma.sync.aligned.m16n8k8.row.col.f32.tf32.tf32.f32 "
        "{%0,%1,%2,%3},{%4,%5,%6,%7},{%8,%9},{%0,%1,%2,%3};"
        : "+f"(c[0]), "+f"(c[1]), "+f"(c[2]), "+f"(c[3])
        : "r"(a[0]), "r"(a[1]), "r"(a[2]), "r"(a[3]), "r"(b[0]), "r"(b[1]));
}

// ---------------- grid barrier (monotonic counter) ----------------
__device__ __forceinline__ unsigned ldacq(const unsigned* p) {
    unsigned v;
    asm volatile("ld.acquire.gpu.global.u32 %0, [%1];" : "=r"(v) : "l"(p));
    return v;
}
__device__ __forceinline__ void gsync(unsigned &target) {
    __syncthreads();
    if (threadIdx.x == 0) {
        __threadfence();
        atomicAdd(&g_barCnt, 1u);
        target += NBLK;
        while (ldacq(&g_barCnt) < target) { }
    }
    __syncthreads();
}

// ---------------- prep kernels (merged into 2) ----------------
// regions: [0,WOUTB) Wout cvt | +12288 Wih perm | +12288 Whh perm | +4096 Wproj | +12 biases
__global__ void k_prepA(const float* __restrict__ W_out, const float* __restrict__ W_ih,
                        const float* __restrict__ W_hh, const float* __restrict__ W_proj,
                        const float* __restrict__ b_ih, const float* __restrict__ b_hh) {
    int blk = blockIdx.x, tid = threadIdx.x;
    if (blk < WOUTB) {
        size_t i = (size_t)blk * 256 + tid;
        g_Wout[i] = __float2bfloat16_rn(W_out[i]);
    } else if (blk < WOUTB + 12288) {
        int i = (blk - WOUTB) * 256 + tid;
        int srow = i >> 10, k = i & 1023;
        int g = srow >> 10, h = srow & 1023;
        g_Wih3[((size_t)(3*h + g) << 10) | k] = __float2bfloat16_rn(W_ih[i]);
    } else if (blk < WOUTB + 24576) {
        int i = (blk - WOUTB - 12288) * 256 + tid;
        int srow = i >> 10, k = i & 1023;
        int g = srow >> 10, h = srow & 1023;
        g_Whh3f[((size_t)(3*h + g) << 10) | k] = W_hh[i];
    } else if (blk < WOUTB + 24576 + 4096) {
        int i = (blk - WOUTB - 24576) * 256 + tid;
        int j = i >> 10, k = i & 1023;
        g_Wp1[i]  = __float2bfloat16_rn(W_proj[(size_t)j * 2048 + k]);
        g_Wp2f[i] = W_proj[(size_t)j * 2048 + 1024 + k];
    } else {
        int i = (blk - WOUTB - 24576 - 4096) * 256 + tid;
        if (i < G3) {
            int g = i >> 10, h = i & 1023;
            g_bih3[3*h + g] = b_ih[i];
            g_bhh3[3*h + g] = b_hh[i];
        }
    }
}
__global__ void k_prepB(const int* __restrict__ input, const float* __restrict__ emb,
                        const float* __restrict__ memory) {
    int blk = blockIdx.x, tid = threadIdx.x;
    if (blk == 0 && tid == 0) g_barCnt = 0;
    if (blk < 8192) {                       // relu(emb[input]) rows (t*B+b)
        int idx = blk * 256 + tid;
        int r = idx >> 10, h = idx & 1023;
        int t = r >> 5, b = r & 31;
        int tok = input[b * TN + t];
        float v = emb[(size_t)tok * HID + h];
        g_xbf[idx] = __float2bfloat16_rn(v > 0.f ? v : 0.f);
    } else {                                // ring init S[k] = memory[31-k]
        int idx = (blk - 8192) * 256 + tid;
        int k = idx >> 15, rest = idx & 32767;
        float v = memory[(size_t)(31 - k) * SLOT + rest];
        g_S[idx] = v;
        g_Sbf[idx] = __float2bfloat16_rn(v);
    }
}

// ---------------- bf16 128x128 GEMM body, cp.async 2-stage pipelined ----------------
__device__ __forceinline__ void gemm_prefetch(
    const __nv_bfloat16* A, const __nv_bfloat16* Wt, int m0, int n0, int k0,
    __nv_bfloat16 (*As)[40], __nv_bfloat16 (*Bs)[40], int tid)
{
#pragma unroll
    for (int v = 0; v < 2; v++) {
        int task = tid + v * 256;
        int row = task >> 2, seg = task & 3;
        cpa16(&As[row][seg * 8], &A [(size_t)(m0 + row) * 1024 + k0 + seg * 8]);
        cpa16(&Bs[row][seg * 8], &Wt[(size_t)(n0 + row) * 1024 + k0 + seg * 8]);
    }
    CPA_COMMIT();
}

__device__ __forceinline__ void gemm128_body(
    const __nv_bfloat16* __restrict__ A, const __nv_bfloat16* __restrict__ Wt,
    const float* __restrict__ bias, float* __restrict__ C, int N, int m0, int n0,
    __nv_bfloat16 (*As2)[128][40], __nv_bfloat16 (*Bs2)[128][40])
{
    const int tid = threadIdx.x, lane = tid & 31, wid = tid >> 5;
    const int wm = (wid & 1) * 64;
    const int wn = (wid >> 1) * 32;
    float acc[4][4][4] = {};

    gemm_prefetch(A, Wt, m0, n0, 0, As2[0], Bs2[0], tid);
    for (int it = 0; it < 32; it++) {
        CPA_WAIT0();
        __syncthreads();
        if (it < 31)
            gemm_prefetch(A, Wt, m0, n0, (it + 1) * 32, As2[(it + 1) & 1], Bs2[(it + 1) & 1], tid);
        __nv_bfloat16 (*As)[40] = As2[it & 1];
        __nv_bfloat16 (*Bs)[40] = Bs2[it & 1];
#pragma unroll
        for (int kk = 0; kk < 32; kk += 16) {
            unsigned af[4][4], bfm[4][2];
#pragma unroll
            for (int mi = 0; mi < 4; mi++)
                ldmx4(af[mi], su32(&As[wm + mi * 16 + (lane & 15)][kk + (lane >> 4) * 8]));
#pragma unroll
            for (int ni = 0; ni < 4; ni++)
                ldmx2(bfm[ni], su32(&Bs[wn + ni * 8 + (lane & 7)][kk + ((lane >> 3) & 1) * 8]));
#pragma unroll
            for (int mi = 0; mi < 4; mi++)
#pragma unroll
                for (int ni = 0; ni < 4; ni++)
                    mma16816(acc[mi][ni], af[mi], bfm[ni]);
        }
    }
#pragma unroll
    for (int mi = 0; mi < 4; mi++)
#pragma unroll
        for (int ni = 0; ni < 4; ni++) {
            int row = m0 + wm + mi * 16 + (lane >> 2);
            int col = n0 + wn + ni * 8 + (lane & 3) * 2;
            float b0 = bias[col], b1 = bias[col + 1];
            C[(size_t)row * N + col]           = acc[mi][ni][0] + b0;
            C[(size_t)row * N + col + 1]       = acc[mi][ni][1] + b1;
            C[(size_t)(row + 8) * N + col]     = acc[mi][ni][2] + b0;
            C[(size_t)(row + 8) * N + col + 1] = acc[mi][ni][3] + b1;
        }
}

// gi (y<24) + projA (y>=24) in one launch
__global__ __launch_bounds__(256) void k_gemm_all(const float* __restrict__ b_proj)
{
    __shared__ __align__(16) __nv_bfloat16 As2[2][128][40];
    __shared__ __align__(16) __nv_bfloat16 Bs2[2][128][40];
    int m0 = blockIdx.x * 128;
    if (blockIdx.y < 24)
        gemm128_body(g_xbf, g_Wih3, g_bih3, g_giAll, G3, m0, blockIdx.y * 128, As2, Bs2);
    else
        gemm128_body(g_xbf, g_Wp1, b_proj, g_projA, HID, m0, (blockIdx.y - 24) * 128, As2, Bs2);
}
// vocab projection
__global__ __launch_bounds__(256) void k_gemm_voc(const float* __restrict__ b_out)
{
    __shared__ __align__(16) __nv_bfloat16 As2[2][128][40];
    __shared__ __align__(16) __nv_bfloat16 Bs2[2][128][40];
    gemm128_body(g_Sbf + (size_t)MEMN * SLOT, g_Wout, b_out, g_logits, VOC,
                 blockIdx.x * 128, blockIdx.y * 128, As2, Bs2);
}

// ---------------- persistent recurrence kernel ----------------
// smem: wWp2[8][1028] | wWhh[24][1028] | As2[2][32][132] | red[8*32*24] | dots[32]
#define SM_RECUR ((8*1028 + 24*1028 + 2*32*132) * 4 + 8*32*24*4 + 128)

__global__ __launch_bounds__(256, 1) void k_recur()
{
    extern __shared__ __align__(16) char sm_raw[];
    uint32_t* wWp2 = (uint32_t*)sm_raw;            // [8][1028]
    uint32_t* wWhh = wWp2 + 8 * 1028;              // [24][1028]
    uint32_t* As2  = wWhh + 24 * 1028;             // [2][32][132]
    float*    red  = (float*)(As2 + 2 * 32 * 132); // [8][32][24]
    float*    dots = red + 8 * 32 * 24;            // [32]

    const int tid = threadIdx.x, blk = blockIdx.x;
    const int lane = tid & 31, wid = tid >> 5;
    const int r4 = lane >> 2, c4 = lane & 3;
    const int n0p = blk * 8, n0g = blk * 24, h0 = blk * 8;

    // cache weight slices as tf32 in smem (once)
    for (int i = tid; i < 8 * 1024; i += 256) {
        int r = i >> 10, k = i & 1023;
        wWp2[r * 1028 + k] = f2tf(g_Wp2f[(size_t)(n0p + r) * 1024 + k]);
    }
    for (int i = tid; i < 24 * 1024; i += 256) {
        int r = i >> 10, k = i & 1023;
        wWhh[r * 1028 + k] = f2tf(g_Whh3f[(size_t)(n0g + r) * 1024 + k]);
    }
    __syncthreads();

    unsigned target = 0;

    for (int t = 0; t < TN; t++) {
        // ===== phase P: proj(32x1024) = mem0 @ Wp2^T + projA[t], 8 cols/block =====
        {
            const float* Ap = g_S + (size_t)(t + 31) * SLOT;
            float accP[2][4] = {};
            float4 regs[4];
#pragma unroll
            for (int v = 0; v < 4; v++) {
                int idx = tid + v * 256;
                regs[v] = __ldcg((const float4*)&Ap[(size_t)(idx >> 5) * 1024 + (idx & 31) * 4]);
            }
            for (int c = 0; c < 8; c++) {
                uint32_t* Ab = As2 + (c & 1) * (32 * 132);
#pragma unroll
                for (int v = 0; v < 4; v++) {
                    int idx = tid + v * 256, row = idx >> 5, seg = idx & 31;
                    uint4 u;
                    u.x = f2tf(regs[v].x); u.y = f2tf(regs[v].y);
                    u.z = f2tf(regs[v].z); u.w = f2tf(regs[v].w);
                    *(uint4*)&Ab[row * 132 + seg * 4] = u;
                }
                __syncthreads();
                if (c < 7) {
#pragma unroll
                    for (int v = 0; v < 4; v++) {
                        int idx = tid + v * 256;
                        regs[v] = __ldcg((const float4*)&Ap[(size_t)(idx >> 5) * 1024 + (c + 1) * 128 + (idx & 31) * 4]);
                    }
                }
                int kb = wid * 16;
#pragma unroll
                for (int ks = 0; ks < 16; ks += 8) {
                    int kl = kb + ks, kg = c * 128 + kl;
                    uint32_t af[2][4], bf2[2];
#pragma unroll
                    for (int mi = 0; mi < 2; mi++) {
                        af[mi][0] = Ab[(mi * 16 + r4) * 132 + kl + c4];
                        af[mi][1] = Ab[(mi * 16 + r4 + 8) * 132 + kl + c4];
                        af[mi][2] = Ab[(mi * 16 + r4) * 132 + kl + c4 + 4];
                        af[mi][3] = Ab[(mi * 16 + r4 + 8) * 132 + kl + c4 + 4];
                    }
                    bf2[0] = wWp2[r4 * 1028 + kg + c4];
                    bf2[1] = wWp2[r4 * 1028 + kg + c4 + 4];
                    mma1688tf(accP[0], af[0], bf2);
                    mma1688tf(accP[1], af[1], bf2);
                }
            }
            {   // cross-warp partials
                float* pr = red + wid * 256;
                int cb = (lane & 3) * 2;
#pragma unroll
                for (int mi = 0; mi < 2; mi++) {
                    int rr = mi * 16 + r4;
                    pr[rr * 8 + cb]           = accP[mi][0];
                    pr[rr * 8 + cb + 1]       = accP[mi][1];
                    pr[(rr + 8) * 8 + cb]     = accP[mi][2];
                    pr[(rr + 8) * 8 + cb + 1] = accP[mi][3];
                }
            }
            __syncthreads();
            {
                int row = tid >> 3, col = tid & 7;
                float s = 0.f;
#pragma unroll
                for (int w = 0; w < 8; w++) s += red[w * 256 + row * 8 + col];
                s += g_projA[(size_t)t * SLOT + row * 1024 + n0p + col];
                g_proj[row * 1024 + n0p + col] = s;
            }
        }
        gsync(target);

        // ===== phase A: attention, blocks 0..31 (one per batch) =====
        if (blk < BAT) {
            const int b = blk;
            float* projS = (float*)As2;
#pragma unroll
            for (int p = 0; p < 4; p++)
                projS[tid + p * 256] = __ldcg(&g_proj[b * HID + tid + p * 256]);
            __syncthreads();
#pragma unroll
            for (int s = 0; s < 4; s++) {
                int m = wid * 4 + s;
                const float* mrow = g_S + (size_t)(t + 31 - m) * SLOT + b * HID;
                float sum = 0.f;
#pragma unroll
                for (int j = 0; j < 32; j++)
                    sum += __ldcg(&mrow[lane + 32 * j]) * projS[lane + 32 * j];
#pragma unroll
                for (int o = 16; o; o >>= 1) sum += __shfl_xor_sync(~0u, sum, o);
                if (lane == 0) dots[m] = sum * 0.03125f;   // 1/sqrt(1024)
            }
            __syncthreads();
            if (wid == 0) {
                float d = dots[lane], mx = d;
#pragma unroll
                for (int o = 16; o; o >>= 1) mx = fmaxf(mx, __shfl_xor_sync(~0u, mx, o));
                float e = expf(d - mx), ss = e;
#pragma unroll
                for (int o = 16; o; o >>= 1) ss += __shfl_xor_sync(~0u, ss, o);
                dots[lane] = e / ss;
            }
            __syncthreads();
#pragma unroll
            for (int p = 0; p < 4; p++) {
                int h = tid + p * 256;
                float acc = 0.f;
#pragma unroll
                for (int m = 0; m < 32; m++)
                    acc += dots[m] * __ldcg(&g_S[(size_t)(t + 31 - m) * SLOT + b * HID + h]);
                g_sel[b * HID + h] = acc;
            }
        }
        gsync(target);

        // ===== phase G: gh = sel @ Whh^T (24 gate-cols/block), gates, write h =====
        {
            float accG[2][3][4] = {};
            float4 regs[4];
#pragma unroll
            for (int v = 0; v < 4; v++) {
                int idx = tid + v * 256;
                regs[v] = __ldcg((const float4*)&g_sel[(size_t)(idx >> 5) * 1024 + (idx & 31) * 4]);
            }
            for (int c = 0; c < 8; c++) {
                uint32_t* Ab = As2 + (c & 1) * (32 * 132);
#pragma unroll
                for (int v = 0; v < 4; v++) {
                    int idx = tid + v * 256, row = idx >> 5, seg = idx & 31;
                    uint4 u;
                    u.x = f2tf(regs[v].x); u.y = f2tf(regs[v].y);
                    u.z = f2tf(regs[v].z); u.w = f2tf(regs[v].w);
                    *(uint4*)&Ab[row * 132 + seg * 4] = u;
                }
                __syncthreads();
                if (c < 7) {
#pragma unroll
                    for (int v = 0; v < 4; v++) {
                        int idx = tid + v * 256;
                        regs[v] = __ldcg((const float4*)&g_sel[(size_t)(idx >> 5) * 1024 + (c + 1) * 128 + (idx & 31) * 4]);
                    }
                }
                int kb = wid * 16;
#pragma unroll
                for (int ks = 0; ks < 16; ks += 8) {
                    int kl = kb + ks, kg = c * 128 + kl;
                    uint32_t af[2][4];
#pragma unroll
                    for (int mi = 0; mi < 2; mi++) {
                        af[mi][0] = Ab[(mi * 16 + r4) * 132 + kl + c4];
                        af[mi][1] = Ab[(mi * 16 + r4 + 8) * 132 + kl + c4];
                        af[mi][2] = Ab[(mi * 16 + r4) * 132 + kl + c4 + 4];
                        af[mi][3] = Ab[(mi * 16 + r4 + 8) * 132 + kl + c4 + 4];
                    }
#pragma unroll
                    for (int ni = 0; ni < 3; ni++) {
                        uint32_t bf2[2] = { wWhh[(ni * 8 + r4) * 1028 + kg + c4],
                                            wWhh[(ni * 8 + r4) * 1028 + kg + c4 + 4] };
                        mma1688tf(accG[0][ni], af[0], bf2);
                        mma1688tf(accG[1][ni], af[1], bf2);
                    }
                }
            }
            {
                float* pr = red + wid * 768;
                int cb = (lane & 3) * 2;
#pragma unroll
                for (int mi = 0; mi < 2; mi++)
#pragma unroll
                    for (int ni = 0; ni < 3; ni++) {
                        int rr = mi * 16 + r4, cc = ni * 8 + cb;
                        pr[rr * 24 + cc]           = accG[mi][ni][0];
                        pr[rr * 24 + cc + 1]       = accG[mi][ni][1];
                        pr[(rr + 8) * 24 + cc]     = accG[mi][ni][2];
                        pr[(rr + 8) * 24 + cc + 1] = accG[mi][ni][3];
                    }
            }
            __syncthreads();
            {
                int b = tid >> 3, hh = tid & 7;
                float gg[3];
#pragma unroll
                for (int g = 0; g < 3; g++) {
                    float s = g_bhh3[n0g + 3 * hh + g];
#pragma unroll
                    for (int w = 0; w < 8; w++) s += red[w * 768 + b * 24 + 3 * hh + g];
                    gg[g] = s;
                }
                const float* gi = g_giAll + (size_t)(t * BAT + b) * G3 + n0g + 3 * hh;
                float r = 1.f / (1.f + expf(-(gi[0] + gg[0])));
                float z = 1.f / (1.f + expf(-(gi[1] + gg[1])));
                float n = tanhf(gi[2] + r * gg[2]);
                float sv = __ldcg(&g_sel[b * HID + h0 + hh]);
                float hv = (1.f - z) * n + z * sv;
                size_t o = (size_t)(MEMN + t) * SLOT + b * HID + h0 + hh;
                g_S[o] = hv;
                g_Sbf[o] = __float2bfloat16_rn(hv);
            }
        }
        gsync(target);
    }
}

// ---------------- log-softmax + outputs ----------------
__global__ __launch_bounds__(256) void k_lse()
{
    const int r = blockIdx.x;
    const float* row = g_logits + (size_t)r * VOC;
    __shared__ float red[8];
    __shared__ float bc;
    int tid = threadIdx.x, lane = tid & 31, wid = tid >> 5;
    float m = -1e30f;
    for (int i = tid; i < VOC; i += 256) m = fmaxf(m, row[i]);
#pragma unroll
    for (int o = 16; o; o >>= 1) m = fmaxf(m, __shfl_xor_sync(~0u, m, o));
    if (lane == 0) red[wid] = m;
    __syncthreads();
    if (tid == 0) {
        float mm = red[0];
        for (int w = 1; w < 8; w++) mm = fmaxf(mm, red[w]);
        bc = mm;
    }
    __syncthreads();
    float M = bc;
    float s = 0.f;
    for (int i = tid; i < VOC; i += 256) s += expf(row[i] - M);
#pragma unroll
    for (int o = 16; o; o >>= 1) s += __shfl_xor_sync(~0u, s, o);
    if (lane == 0) red[wid] = s;
    __syncthreads();
    if (tid == 0) {
        float ss = 0.f;
        for (int w = 0; w < 8; w++) ss += red[w];
        g_lse[r] = M + logf(ss);
    }
}

__global__ __launch_bounds__(256) void k_out(float* __restrict__ out)
{
    const int r = blockIdx.x;            // r = t*BAT + b
    const int t = r >> 5, b = r & 31;
    const float l = g_lse[r];
    const float4* src = (const float4*)(g_logits + (size_t)r * VOC);
    float4* dst = (float4*)(out + ((size_t)b * TN + t) * VOC);
    for (int i = threadIdx.x; i < VOC / 4; i += 256) {
        float4 v = src[i];
        v.x -= l; v.y -= l; v.z -= l; v.w -= l;
        dst[i] = v;
    }
}

// out2 (MEM,B,H): out2[m][b][h] = S[95-m][b][h]
__global__ void k_outmem(float* __restrict__ out2)
{
    int idx = blockIdx.x * 256 + threadIdx.x;
    int m = idx / (SLOT / 4);
    int rest = idx % (SLOT / 4);
    const float4* src = (const float4*)(g_S + (size_t)(MEMN + TN - 1 - m) * SLOT);
    float4* dst = (float4*)(out2 + (size_t)m * SLOT);
    dst[rest] = src[rest];
}

// ---------------- launch ----------------
extern "C" void kernel_launch(void* const* d_in, const int* in_sizes, int n_in,
                              void* d_out, int out_size)
{
    const int*   input  = (const int*)  d_in[0];
    const float* memory = (const float*)d_in[1];
    const float* emb    = (const float*)d_in[2];
    const float* W_proj = (const float*)d_in[3];
    const float* b_proj = (const float*)d_in[4];
    const float* W_ih   = (const float*)d_in[5];
    const float* W_hh   = (const float*)d_in[6];
    const float* b_ih   = (const float*)d_in[7];
    const float* b_hh   = (const float*)d_in[8];
    const float* W_out  = (const float*)d_in[9];
    const float* b_out  = (const float*)d_in[10];
    float* out = (float*)d_out;

    cudaFuncSetAttribute(k_recur, cudaFuncAttributeMaxDynamicSharedMemorySize, SM_RECUR);

    k_prepA<<<WOUTB + 24576 + 4096 + 12, 256>>>(W_out, W_ih, W_hh, W_proj, b_ih, b_hh);  // 1
    k_prepB<<<8192 + 4096, 256>>>(input, emb, memory);                                   // 2
    k_gemm_all<<<dim3(16, 32), 256>>>(b_proj);                                           // 3
    k_recur<<<NBLK, 256, SM_RECUR>>>();                                                  // 4
    k_gemm_voc<<<dim3(16, 250), 256>>>(b_out);                                           // 5
    k_lse<<<RN, 256>>>();                                                                // 6
    k_out<<<RN, 256>>>(out);                                                             // 7
    k_outmem<<<(MEMN * SLOT / 4) / 256, 256>>>(out + (size_t)BAT * TN * VOC);            // 8
}